// round 15
// baseline (speedup 1.0000x reference)
#include <cuda_runtime.h>
#include <cuda_bf16.h>
#include <cstdint>
#include <cstddef>

// Problem: VQ-VAE quantizer
// inputs: (32, 64, 64, 64) f32 NCHW ; emb_weight: (512, 64) f32
// Outputs (f32): loss(1) | quantized(8388608) | encoding_indices(131072) | perplexity(1) | codes(131072)
#define NB   32
#define NC   64
#define NHW  4096
#define NROW 131072
#define NK   512

#define OFF_LOSS  0
#define OFF_Q     1
#define OFF_IDX   8388609
#define OFF_PERP  8519681
#define OFF_CODES 8519682

typedef unsigned long long ULL;

// ---------------------------------------------------------------------------
// f32x2 packed-math helpers (plain PTX on Blackwell targets)
// ---------------------------------------------------------------------------
__device__ __forceinline__ ULL f32x2_fma(ULL a, ULL b, ULL c) {
    ULL d;
    asm("fma.rn.f32x2 %0, %1, %2, %3;" : "=l"(d) : "l"(a), "l"(b), "l"(c));
    return d;
}
__device__ __forceinline__ ULL f32x2_bcast(float v) {
    ULL r;
    asm("mov.b64 %0, {%1, %2};" : "=l"(r) : "f"(v), "f"(v));
    return r;
}
__device__ __forceinline__ float2 f32x2_unpack(ULL v) {
    float2 r;
    asm("mov.b64 {%0, %1}, %2;" : "=f"(r.x), "=f"(r.y) : "l"(v));
    return r;
}

// ---------------------------------------------------------------------------
// Scratch
// ---------------------------------------------------------------------------
__device__ int   g_idx[NROW];
__device__ float g_counts[NK];
__device__ float g_hn[NK];         // 0.5 * ||e||^2
__device__ float g_rowd[NROW];     // per-row ||x - e_best||^2 (exact fp32)
__device__ float g_lpart[256];     // loss partial sums

// ---------------------------------------------------------------------------
// Kernel 0: init — half-norms of codes, zero histogram
// ---------------------------------------------------------------------------
__global__ void vq_init(const float* __restrict__ emb) {
    int t = threadIdx.x;               // 512 threads
    const float4* e = (const float4*)(emb + t * NC);
    float s = 0.f;
#pragma unroll
    for (int i = 0; i < 16; i++) {
        float4 v = e[i];
        s += v.x * v.x + v.y * v.y + v.z * v.z + v.w * v.w;
    }
    g_hn[t] = 0.5f * s;
    g_counts[t] = 0.f;
}

// ---------------------------------------------------------------------------
// Kernel 1: exact fp32 FFMA2 argmin.
// CTA = 64 rows x 512 codes, 128 threads, smem 34KB, 5 CTAs/SM target.
// Thread tile: 8 rows x 4 codes; rows in quads via LDS.128, fma2 row-pairs.
// Code tiles of 64 (8 tiles cover K=512). C=64 is the full reduction dim.
// ---------------------------------------------------------------------------
__global__ void __launch_bounds__(128, 5)
vq_argmin(const float* __restrict__ x_in, const float* __restrict__ emb) {
    extern __shared__ float sm[];
    float (*xs)[64] = (float (*)[64])sm;                  // [64][64]  = 16 KB
    float (*es)[68] = (float (*)[68])(sm + 64 * 64);      // [64][68]  = 17 KB (padded)
    float* hn_s = sm + 64 * 64 + 64 * 68;                 // [64]
    float* rvs  = (float*)es;                             // overlay: 16*64 floats
    int*   ris  = ((int*)es) + 16 * 64;                   // overlay: 16*64 ints

    const int tid = threadIdx.x;
    const int rg  = tid & 7;           // row group: quads {4rg..4rg+3, 4rg+32..}
    const int cg  = tid >> 3;          // code group 0..15 (4 codes)
    const int n0  = blockIdx.x * 64;
    const int b   = n0 >> 12;
    const int hw0 = n0 & 4095;

    // Load x tile transposed: xs[c][m] = inputs[b][c][hw0+m]  (coalesced)
    const float* xbase = x_in + (size_t)b * (NC * NHW) + hw0;
    for (int i = tid; i < 64 * 64; i += 128) {
        int c = i >> 6, m = i & 63;
        xs[c][m] = xbase[(size_t)c * NHW + m];
    }

    float bestv[8];
    int   besti[8];
#pragma unroll
    for (int j = 0; j < 8; j++) { bestv[j] = -3.4e38f; besti[j] = 0; }

    for (int ct = 0; ct < 8; ct++) {
        __syncthreads();  // protect es/hn_s from previous tile's readers
        // Load 64-code tile transposed: es[c][code]
        const float* ebase = emb + (size_t)ct * 64 * NC;
        for (int i = tid; i < 64 * 64; i += 128) {
            es[i & 63][i >> 6] = ebase[i];
        }
        if (tid < 64) hn_s[tid] = g_hn[ct * 64 + tid];
        __syncthreads();

        ULL acc[4][4];     // [row-pair][code] ; pairs: (4rg+2p, +1), (4rg+32+2p, +1)
#pragma unroll
        for (int j = 0; j < 4; j++)
#pragma unroll
            for (int c = 0; c < 4; c++) acc[j][c] = 0ull;

#pragma unroll 8
        for (int k = 0; k < 64; k++) {
            // two LDS.128: row quads [4rg..4rg+3] and [4rg+32..4rg+35]
            float4 xa = *(const float4*)&xs[k][4 * rg];
            float4 xb = *(const float4*)&xs[k][4 * rg + 32];
            ULL xv[4];
            xv[0] = *(const ULL*)&xa.x;     // rows (4rg, 4rg+1)
            xv[1] = *(const ULL*)&xa.z;     // rows (4rg+2, 4rg+3)
            xv[2] = *(const ULL*)&xb.x;     // rows (4rg+32, 4rg+33)
            xv[3] = *(const ULL*)&xb.z;     // rows (4rg+34, 4rg+35)
            float4 ea = *(const float4*)&es[k][cg * 4];
            ULL ep[4];
            ep[0] = f32x2_bcast(ea.x); ep[1] = f32x2_bcast(ea.y);
            ep[2] = f32x2_bcast(ea.z); ep[3] = f32x2_bcast(ea.w);
#pragma unroll
            for (int j = 0; j < 4; j++)
#pragma unroll
                for (int c = 0; c < 4; c++)
                    acc[j][c] = f32x2_fma(xv[j], ep[c], acc[j][c]);
        }

        // Per-tile epilogue: score = dot - 0.5||e||^2 ; running argmax
        // (ascending code order -> reference first-min tie semantics)
#pragma unroll
        for (int c = 0; c < 4; c++) {
            float h = hn_s[cg * 4 + c];
            int code = ct * 64 + cg * 4 + c;
#pragma unroll
            for (int j = 0; j < 4; j++) {
                float2 a = f32x2_unpack(acc[j][c]);
                // local row index 0..7 for pair j: (2j, 2j+1)
                float s0 = a.x - h, s1 = a.y - h;
                if (s0 > bestv[2 * j])     { bestv[2 * j]     = s0; besti[2 * j]     = code; }
                if (s1 > bestv[2 * j + 1]) { bestv[2 * j + 1] = s1; besti[2 * j + 1] = code; }
            }
        }
    }

    __syncthreads();  // all done reading es -> safe to overlay reduce arrays
#pragma unroll
    for (int j = 0; j < 4; j++) {
#pragma unroll
        for (int p = 0; p < 2; p++) {
            int row = (j < 2) ? (4 * rg + 2 * j + p) : (4 * rg + 32 + 2 * (j - 2) + p);
            rvs[cg * 64 + row] = bestv[2 * j + p];
            ris[cg * 64 + row] = besti[2 * j + p];
        }
    }
    __syncthreads();

    if (tid < 64) {
        int row = tid;
        float bv = rvs[row];
        int   bi = ris[row];
#pragma unroll
        for (int g = 1; g < 16; g++) {
            float v = rvs[g * 64 + row];
            if (v > bv) { bv = v; bi = ris[g * 64 + row]; }
        }
        // ||x||^2 for this row (xs intact)
        float xn = 0.f;
#pragma unroll
        for (int k = 0; k < 64; k++) { float xv = xs[k][row]; xn += xv * xv; }
        int n = n0 + row;
        g_idx[n]  = bi;
        g_rowd[n] = xn - 2.f * bv;       // = ||x - e_best||^2 (exact fp32 scores)
        atomicAdd(&g_counts[bi], 1.0f);  // integer-valued float adds: exact
    }
}

// ---------------------------------------------------------------------------
// Kernel 2: gather quantized output (NCHW) + index outputs (L2-direct, no smem)
// ---------------------------------------------------------------------------
__global__ void __launch_bounds__(256)
vq_gather(const float* __restrict__ emb, float* __restrict__ out) {
    int n = blockIdx.x * 256 + threadIdx.x;
    int idx = g_idx[n];
    const float4* cr = (const float4*)(emb + (size_t)idx * NC);

    int b = n >> 12, hw = n & 4095;
    float* qb = out + OFF_Q + (size_t)b * (NC * NHW) + hw;
#pragma unroll
    for (int q = 0; q < 16; q++) {
        float4 v = __ldg(cr + q);
        qb[(size_t)(4 * q + 0) * NHW] = v.x;   // consecutive threads -> consecutive hw
        qb[(size_t)(4 * q + 1) * NHW] = v.y;
        qb[(size_t)(4 * q + 2) * NHW] = v.z;
        qb[(size_t)(4 * q + 3) * NHW] = v.w;
    }
    float fidx = (float)idx;
    out[OFF_IDX + n]   = fidx;
    out[OFF_CODES + n] = fidx;
}

// ---------------------------------------------------------------------------
// Kernel 3: parallel loss partials (deterministic per-block fixed-order sums)
// ---------------------------------------------------------------------------
__global__ void __launch_bounds__(256)
vq_rowsum(void) {
    __shared__ float sr[256];
    int t = threadIdx.x;
    int base = blockIdx.x * 512;       // 256 blocks x 512 rows
    sr[t] = g_rowd[base + t] + g_rowd[base + 256 + t];
    __syncthreads();
#pragma unroll
    for (int o = 128; o >= 1; o >>= 1) {
        if (t < o) sr[t] += sr[t + o];
        __syncthreads();
    }
    if (t == 0) g_lpart[blockIdx.x] = sr[0];
}

// ---------------------------------------------------------------------------
// Kernel 4: finalize loss + perplexity (tiny, deterministic)
// ---------------------------------------------------------------------------
__global__ void vq_finalize(float* __restrict__ out) {
    __shared__ float sp[512];
    __shared__ float sl[256];
    int t = threadIdx.x;
    float p = g_counts[t] * (1.0f / (float)NROW);
    sp[t] = p * logf(p + 1e-10f);
    if (t < 256) sl[t] = g_lpart[t];
    __syncthreads();
#pragma unroll
    for (int o = 256; o >= 1; o >>= 1) {
        if (t < o) {
            sp[t] += sp[t + o];
            if (o <= 128) sl[t] += sl[t + o];
        }
        __syncthreads();
    }
    if (t == 0) {
        out[OFF_PERP] = expf(-sp[0]);
        out[OFF_LOSS] = 0.25f * sl[0] * (1.0f / 8388608.0f);  // BETA * mean over N*C
    }
}

// ---------------------------------------------------------------------------
// Launch
// ---------------------------------------------------------------------------
extern "C" void kernel_launch(void* const* d_in, const int* in_sizes, int n_in,
                              void* d_out, int out_size) {
    const float* x = (const float*)d_in[0];
    const float* e = (const float*)d_in[1];
    if (n_in >= 2 && in_sizes[0] == NK * NC) {
        const float* tmp = x; x = e; e = tmp;
    }
    float* out = (float*)d_out;

    const int SMEM1 = (64 * 64 + 64 * 68 + 64) * (int)sizeof(float);  // 34048 B
    cudaFuncSetAttribute(vq_argmin, cudaFuncAttributeMaxDynamicSharedMemorySize, SMEM1);

    vq_init<<<1, 512>>>(e);
    vq_argmin<<<NROW / 64, 128, SMEM1>>>(x, e);
    vq_gather<<<NROW / 256, 256>>>(e, out);
    vq_rowsum<<<256, 256>>>();
    vq_finalize<<<1, 512>>>(out);
}

// round 16
// speedup vs baseline: 1.2024x; 1.2024x over previous
#include <cuda_runtime.h>
#include <cuda_bf16.h>
#include <cstdint>
#include <cstddef>

// Problem: VQ-VAE quantizer
// inputs: (32, 64, 64, 64) f32 NCHW ; emb_weight: (512, 64) f32
// Outputs (f32): loss(1) | quantized(8388608) | encoding_indices(131072) | perplexity(1) | codes(131072)
#define NB   32
#define NC   64
#define NHW  4096
#define NROW 131072
#define NK   512

#define OFF_LOSS  0
#define OFF_Q     1
#define OFF_IDX   8388609
#define OFF_PERP  8519681
#define OFF_CODES 8519682

typedef unsigned long long ULL;

// ---------------------------------------------------------------------------
// f32x2 packed-math helpers (plain PTX on Blackwell targets)
// ---------------------------------------------------------------------------
__device__ __forceinline__ ULL f32x2_fma(ULL a, ULL b, ULL c) {
    ULL d;
    asm("fma.rn.f32x2 %0, %1, %2, %3;" : "=l"(d) : "l"(a), "l"(b), "l"(c));
    return d;
}
__device__ __forceinline__ ULL f32x2_bcast(float v) {
    ULL r;
    asm("mov.b64 %0, {%1, %2};" : "=l"(r) : "f"(v), "f"(v));
    return r;
}
__device__ __forceinline__ float2 f32x2_unpack(ULL v) {
    float2 r;
    asm("mov.b64 {%0, %1}, %2;" : "=f"(r.x), "=f"(r.y) : "l"(v));
    return r;
}

// ---------------------------------------------------------------------------
// Scratch
// ---------------------------------------------------------------------------
__device__ float g_counts[NK];
__device__ float g_hn[NK];         // 0.5 * ||e||^2
__device__ float g_rowd[NROW];     // per-row ||x - e_best||^2 (exact fp32)
__device__ float g_lpart[256];     // loss partial sums

// ---------------------------------------------------------------------------
// Kernel 0: init — half-norms of codes, zero histogram
// ---------------------------------------------------------------------------
__global__ void vq_init(const float* __restrict__ emb) {
    int t = threadIdx.x;               // 512 threads
    const float4* e = (const float4*)(emb + t * NC);
    float s = 0.f;
#pragma unroll
    for (int i = 0; i < 16; i++) {
        float4 v = e[i];
        s += v.x * v.x + v.y * v.y + v.z * v.z + v.w * v.w;
    }
    g_hn[t] = 0.5f * s;
    g_counts[t] = 0.f;
}

// ---------------------------------------------------------------------------
// Kernel 1: exact fp32 FFMA2 argmin + FUSED output writes.
// CTA = 64 rows x 512 codes, 128 threads, smem 50.7KB -> 4 CTAs/SM (R14 shape).
// Thread tile: 8 rows x 8 codes (best MACs-per-LDS-byte ratio).
// Epilogue writes quantized NCHW tile + both index outputs directly (no
// separate gather kernel; stores overlap other CTAs' compute).
// ---------------------------------------------------------------------------
__global__ void __launch_bounds__(128, 4)
vq_argmin(const float* __restrict__ x_in, const float* __restrict__ emb,
          float* __restrict__ out) {
    extern __shared__ float sm[];
    float (*xs)[64]  = (float (*)[64])sm;                  // [64][64]  = 16 KB
    float (*es)[132] = (float (*)[132])(sm + 64 * 64);     // [64][132] = 33 KB (padded)
    float* hn_s = sm + 64 * 64 + 64 * 132;                 // [128]
    float* rvs  = (float*)es;                              // overlay: 16*64 floats
    int*   ris  = ((int*)es) + 16 * 64;                    // overlay: 16*64 ints
    int*   fidx = ((int*)es) + 32 * 64;                    // overlay: 64 final indices

    const int tid = threadIdx.x;
    const int rg  = tid & 7;           // row group 0..7 (8 rows: pairs {2rg+16j, +1})
    const int cg  = tid >> 3;          // code group 0..15 (8 codes)
    const int n0  = blockIdx.x * 64;
    const int b   = n0 >> 12;
    const int hw0 = n0 & 4095;

    // Load x tile transposed: xs[c][m] = inputs[b][c][hw0+m]  (coalesced)
    const float* xbase = x_in + (size_t)b * (NC * NHW) + hw0;
    for (int i = tid; i < 64 * 64; i += 128) {
        int c = i >> 6, m = i & 63;
        xs[c][m] = xbase[(size_t)c * NHW + m];
    }

    float bestv[8];
    int   besti[8];
#pragma unroll
    for (int j = 0; j < 8; j++) { bestv[j] = -3.4e38f; besti[j] = 0; }

    for (int ct = 0; ct < 4; ct++) {
        __syncthreads();  // protect es/hn_s from previous tile's readers
        // Load 128-code tile transposed: es[c][code]
        const float* ebase = emb + (size_t)ct * 128 * NC;
        for (int i = tid; i < 128 * 64; i += 128) {
            es[i & 63][i >> 6] = ebase[i];
        }
        if (tid < 128) hn_s[tid] = g_hn[ct * 128 + tid];
        __syncthreads();

        ULL acc[4][8];
#pragma unroll
        for (int j = 0; j < 4; j++)
#pragma unroll
            for (int c = 0; c < 8; c++) acc[j][c] = 0ull;

#pragma unroll 8
        for (int k = 0; k < 64; k++) {
            ULL xv[4];
#pragma unroll
            for (int j = 0; j < 4; j++)
                xv[j] = *(const ULL*)&xs[k][2 * rg + 16 * j];   // (row, row+1) pair
            float4 ea = *(const float4*)&es[k][cg * 8];
            float4 eb = *(const float4*)&es[k][cg * 8 + 4];
            ULL ep[8];
            ep[0] = f32x2_bcast(ea.x); ep[1] = f32x2_bcast(ea.y);
            ep[2] = f32x2_bcast(ea.z); ep[3] = f32x2_bcast(ea.w);
            ep[4] = f32x2_bcast(eb.x); ep[5] = f32x2_bcast(eb.y);
            ep[6] = f32x2_bcast(eb.z); ep[7] = f32x2_bcast(eb.w);
#pragma unroll
            for (int j = 0; j < 4; j++)
#pragma unroll
                for (int c = 0; c < 8; c++)
                    acc[j][c] = f32x2_fma(xv[j], ep[c], acc[j][c]);
        }

        // Per-tile epilogue: score = dot - 0.5||e||^2 ; running argmax
        // (ascending code order -> reference first-min tie semantics)
#pragma unroll
        for (int c = 0; c < 8; c++) {
            float h = hn_s[cg * 8 + c];
            int code = ct * 128 + cg * 8 + c;
#pragma unroll
            for (int j = 0; j < 4; j++) {
                float2 a = f32x2_unpack(acc[j][c]);
                float s0 = a.x - h, s1 = a.y - h;
                if (s0 > bestv[2 * j])     { bestv[2 * j]     = s0; besti[2 * j]     = code; }
                if (s1 > bestv[2 * j + 1]) { bestv[2 * j + 1] = s1; besti[2 * j + 1] = code; }
            }
        }
    }

    __syncthreads();  // all done reading es -> safe to overlay reduce arrays
#pragma unroll
    for (int j = 0; j < 4; j++) {
#pragma unroll
        for (int p = 0; p < 2; p++) {
            int row = 2 * rg + 16 * j + p;
            rvs[cg * 64 + row] = bestv[2 * j + p];
            ris[cg * 64 + row] = besti[2 * j + p];
        }
    }
    __syncthreads();

    if (tid < 64) {
        int row = tid;
        float bv = rvs[row];
        int   bi = ris[row];
#pragma unroll
        for (int g = 1; g < 16; g++) {
            float v = rvs[g * 64 + row];
            if (v > bv) { bv = v; bi = ris[g * 64 + row]; }
        }
        // ||x||^2 for this row (xs intact)
        float xn = 0.f;
#pragma unroll
        for (int k = 0; k < 64; k++) { float xv = xs[k][row]; xn += xv * xv; }
        int n = n0 + row;
        g_rowd[n] = xn - 2.f * bv;       // = ||x - e_best||^2 (exact fp32 scores)
        atomicAdd(&g_counts[bi], 1.0f);  // integer-valued float adds: exact
        fidx[row] = bi;
        float fb = (float)bi;
        out[OFF_IDX + n]   = fb;
        out[OFF_CODES + n] = fb;
    }
    __syncthreads();

    // ---- fused gather: all 128 threads write the quantized NCHW tile.
    // Thread t: row = t&63, channel half = (t>>6)*32. Stores coalesce across
    // threads (consecutive rows -> consecutive hw for fixed channel).
    {
        int row = tid & 63;
        int ch0 = (tid >> 6) * 32;
        int idx = fidx[row];
        const float4* cr = (const float4*)(emb + (size_t)idx * NC + ch0);
        float* qb = out + OFF_Q + (size_t)b * (NC * NHW) + (size_t)ch0 * NHW + hw0 + row;
#pragma unroll
        for (int q = 0; q < 8; q++) {
            float4 v = __ldg(cr + q);
            qb[(size_t)(4 * q + 0) * NHW] = v.x;
            qb[(size_t)(4 * q + 1) * NHW] = v.y;
            qb[(size_t)(4 * q + 2) * NHW] = v.z;
            qb[(size_t)(4 * q + 3) * NHW] = v.w;
        }
    }
}

// ---------------------------------------------------------------------------
// Kernel 2: parallel loss partials (deterministic per-block fixed-order sums)
// ---------------------------------------------------------------------------
__global__ void __launch_bounds__(256)
vq_rowsum(void) {
    __shared__ float sr[256];
    int t = threadIdx.x;
    int base = blockIdx.x * 512;       // 256 blocks x 512 rows
    sr[t] = g_rowd[base + t] + g_rowd[base + 256 + t];
    __syncthreads();
#pragma unroll
    for (int o = 128; o >= 1; o >>= 1) {
        if (t < o) sr[t] += sr[t + o];
        __syncthreads();
    }
    if (t == 0) g_lpart[blockIdx.x] = sr[0];
}

// ---------------------------------------------------------------------------
// Kernel 3: finalize loss + perplexity (tiny, deterministic)
// ---------------------------------------------------------------------------
__global__ void vq_finalize(float* __restrict__ out) {
    __shared__ float sp[512];
    __shared__ float sl[256];
    int t = threadIdx.x;
    float p = g_counts[t] * (1.0f / (float)NROW);
    sp[t] = p * logf(p + 1e-10f);
    if (t < 256) sl[t] = g_lpart[t];
    __syncthreads();
#pragma unroll
    for (int o = 256; o >= 1; o >>= 1) {
        if (t < o) {
            sp[t] += sp[t + o];
            if (o <= 128) sl[t] += sl[t + o];
        }
        __syncthreads();
    }
    if (t == 0) {
        out[OFF_PERP] = expf(-sp[0]);
        out[OFF_LOSS] = 0.25f * sl[0] * (1.0f / 8388608.0f);  // BETA * mean over N*C
    }
}

// ---------------------------------------------------------------------------
// Launch
// ---------------------------------------------------------------------------
extern "C" void kernel_launch(void* const* d_in, const int* in_sizes, int n_in,
                              void* d_out, int out_size) {
    const float* x = (const float*)d_in[0];
    const float* e = (const float*)d_in[1];
    if (n_in >= 2 && in_sizes[0] == NK * NC) {
        const float* tmp = x; x = e; e = tmp;
    }
    float* out = (float*)d_out;

    const int SMEM1 = (64 * 64 + 64 * 132 + 128) * (int)sizeof(float);  // 50688 B
    cudaFuncSetAttribute(vq_argmin, cudaFuncAttributeMaxDynamicSharedMemorySize, SMEM1);

    vq_init<<<1, 512>>>(e);
    vq_argmin<<<NROW / 64, 128, SMEM1>>>(x, e, out);
    vq_rowsum<<<256, 256>>>();
    vq_finalize<<<1, 512>>>(out);
}

// round 17
// speedup vs baseline: 1.2144x; 1.0100x over previous
#include <cuda_runtime.h>
#include <cuda_bf16.h>
#include <cstdint>
#include <cstddef>

// Problem: VQ-VAE quantizer
// inputs: (32, 64, 64, 64) f32 NCHW ; emb_weight: (512, 64) f32
// Outputs (f32): loss(1) | quantized(8388608) | encoding_indices(131072) | perplexity(1) | codes(131072)
#define NB   32
#define NC   64
#define NHW  4096
#define NROW 131072
#define NK   512
#define NCTA 2048          // argmin CTAs (64 rows each)

#define OFF_LOSS  0
#define OFF_Q     1
#define OFF_IDX   8388609
#define OFF_PERP  8519681
#define OFF_CODES 8519682

typedef unsigned long long ULL;

// ---------------------------------------------------------------------------
// f32x2 packed-math helpers (plain PTX on Blackwell targets)
// ---------------------------------------------------------------------------
__device__ __forceinline__ ULL f32x2_fma(ULL a, ULL b, ULL c) {
    ULL d;
    asm("fma.rn.f32x2 %0, %1, %2, %3;" : "=l"(d) : "l"(a), "l"(b), "l"(c));
    return d;
}
__device__ __forceinline__ ULL f32x2_bcast(float v) {
    ULL r;
    asm("mov.b64 %0, {%1, %2};" : "=l"(r) : "f"(v), "f"(v));
    return r;
}
__device__ __forceinline__ float2 f32x2_unpack(ULL v) {
    float2 r;
    asm("mov.b64 {%0, %1}, %2;" : "=f"(r.x), "=f"(r.y) : "l"(v));
    return r;
}

// ---------------------------------------------------------------------------
// Scratch
// ---------------------------------------------------------------------------
__device__ float g_counts[NK];
__device__ float g_hn[NK];         // 0.5 * ||e||^2
__device__ float g_lpart[NCTA];    // per-CTA loss partial sums (deterministic)

// ---------------------------------------------------------------------------
// Kernel 0: init — half-norms of codes, zero histogram
// ---------------------------------------------------------------------------
__global__ void vq_init(const float* __restrict__ emb) {
    int t = threadIdx.x;               // 512 threads
    const float4* e = (const float4*)(emb + t * NC);
    float s = 0.f;
#pragma unroll
    for (int i = 0; i < 16; i++) {
        float4 v = e[i];
        s += v.x * v.x + v.y * v.y + v.z * v.z + v.w * v.w;
    }
    g_hn[t] = 0.5f * s;
    g_counts[t] = 0.f;
}

// ---------------------------------------------------------------------------
// Kernel 1: exact fp32 FFMA2 argmin + FUSED outputs + FUSED loss partial.
// CTA = 64 rows x 512 codes, 128 threads, smem 50.7KB -> 4 CTAs/SM.
// Thread tile: 8 rows x 8 codes (best MACs-per-LDS-byte ratio).
// Epilogue: writes quantized NCHW tile + both index outputs + one
// deterministic per-CTA loss partial (no g_rowd round-trip, no rowsum kernel).
// ---------------------------------------------------------------------------
__global__ void __launch_bounds__(128, 4)
vq_argmin(const float* __restrict__ x_in, const float* __restrict__ emb,
          float* __restrict__ out) {
    extern __shared__ float sm[];
    float (*xs)[64]  = (float (*)[64])sm;                  // [64][64]  = 16 KB
    float (*es)[132] = (float (*)[132])(sm + 64 * 64);     // [64][132] = 33 KB (padded)
    float* hn_s = sm + 64 * 64 + 64 * 132;                 // [128]
    float* rvs  = (float*)es;                              // overlay: 16*64 floats
    int*   ris  = ((int*)es) + 16 * 64;                    // overlay: 16*64 ints
    int*   fidx = ((int*)es) + 32 * 64;                    // overlay: 64 final indices
    float* dred = (float*)(((int*)es) + 33 * 64);          // overlay: 64 d values

    const int tid = threadIdx.x;
    const int rg  = tid & 7;           // row group 0..7 (8 rows: pairs {2rg+16j, +1})
    const int cg  = tid >> 3;          // code group 0..15 (8 codes)
    const int n0  = blockIdx.x * 64;
    const int b   = n0 >> 12;
    const int hw0 = n0 & 4095;

    // Load x tile transposed: xs[c][m] = inputs[b][c][hw0+m]  (coalesced)
    const float* xbase = x_in + (size_t)b * (NC * NHW) + hw0;
    for (int i = tid; i < 64 * 64; i += 128) {
        int c = i >> 6, m = i & 63;
        xs[c][m] = xbase[(size_t)c * NHW + m];
    }

    float bestv[8];
    int   besti[8];
#pragma unroll
    for (int j = 0; j < 8; j++) { bestv[j] = -3.4e38f; besti[j] = 0; }

    for (int ct = 0; ct < 4; ct++) {
        __syncthreads();  // protect es/hn_s from previous tile's readers
        // Load 128-code tile transposed: es[c][code]  (33-word rows: conflict-free)
        const float* ebase = emb + (size_t)ct * 128 * NC;
        for (int i = tid; i < 128 * 64; i += 128) {
            es[i & 63][i >> 6] = ebase[i];
        }
        if (tid < 128) hn_s[tid] = g_hn[ct * 128 + tid];
        __syncthreads();

        ULL acc[4][8];
#pragma unroll
        for (int j = 0; j < 4; j++)
#pragma unroll
            for (int c = 0; c < 8; c++) acc[j][c] = 0ull;

#pragma unroll 8
        for (int k = 0; k < 64; k++) {
            ULL xv[4];
#pragma unroll
            for (int j = 0; j < 4; j++)
                xv[j] = *(const ULL*)&xs[k][2 * rg + 16 * j];   // (row, row+1) pair
            float4 ea = *(const float4*)&es[k][cg * 8];
            float4 eb = *(const float4*)&es[k][cg * 8 + 4];
            ULL ep[8];
            ep[0] = f32x2_bcast(ea.x); ep[1] = f32x2_bcast(ea.y);
            ep[2] = f32x2_bcast(ea.z); ep[3] = f32x2_bcast(ea.w);
            ep[4] = f32x2_bcast(eb.x); ep[5] = f32x2_bcast(eb.y);
            ep[6] = f32x2_bcast(eb.z); ep[7] = f32x2_bcast(eb.w);
#pragma unroll
            for (int j = 0; j < 4; j++)
#pragma unroll
                for (int c = 0; c < 8; c++)
                    acc[j][c] = f32x2_fma(xv[j], ep[c], acc[j][c]);
        }

        // Per-tile epilogue: score = dot - 0.5||e||^2 ; running argmax
        // (ascending code order -> reference first-min tie semantics)
#pragma unroll
        for (int c = 0; c < 8; c++) {
            float h = hn_s[cg * 8 + c];
            int code = ct * 128 + cg * 8 + c;
#pragma unroll
            for (int j = 0; j < 4; j++) {
                float2 a = f32x2_unpack(acc[j][c]);
                float s0 = a.x - h, s1 = a.y - h;
                if (s0 > bestv[2 * j])     { bestv[2 * j]     = s0; besti[2 * j]     = code; }
                if (s1 > bestv[2 * j + 1]) { bestv[2 * j + 1] = s1; besti[2 * j + 1] = code; }
            }
        }
    }

    __syncthreads();  // all done reading es -> safe to overlay reduce arrays
#pragma unroll
    for (int j = 0; j < 4; j++) {
#pragma unroll
        for (int p = 0; p < 2; p++) {
            int row = 2 * rg + 16 * j + p;
            rvs[cg * 64 + row] = bestv[2 * j + p];
            ris[cg * 64 + row] = besti[2 * j + p];
        }
    }
    __syncthreads();

    if (tid < 64) {
        int row = tid;
        float bv = rvs[row];
        int   bi = ris[row];
#pragma unroll
        for (int g = 1; g < 16; g++) {
            float v = rvs[g * 64 + row];
            if (v > bv) { bv = v; bi = ris[g * 64 + row]; }
        }
        // ||x||^2 for this row (xs intact)
        float xn = 0.f;
#pragma unroll
        for (int k = 0; k < 64; k++) { float xv = xs[k][row]; xn += xv * xv; }
        int n = n0 + row;
        dred[row] = xn - 2.f * bv;       // = ||x - e_best||^2 (exact fp32 scores)
        atomicAdd(&g_counts[bi], 1.0f);  // integer-valued float adds: exact
        fidx[row] = bi;
        float fb = (float)bi;
        out[OFF_IDX + n]   = fb;
        out[OFF_CODES + n] = fb;
    }
    __syncthreads();

    // ---- fused loss partial: deterministic 64-value tree -> g_lpart[block]
    if (tid < 32) {
        dred[tid] += dred[tid + 32];
    }
    __syncthreads();
#pragma unroll
    for (int o = 16; o >= 1; o >>= 1) {
        if (tid < o) dred[tid] += dred[tid + o];
        __syncthreads();
    }
    if (tid == 0) g_lpart[blockIdx.x] = dred[0];

    // ---- fused gather: all 128 threads write the quantized NCHW tile.
    // Thread t: row = t&63, channel half = (t>>6)*32. Stores coalesce across
    // threads (consecutive rows -> consecutive hw for fixed channel).
    {
        int row = tid & 63;
        int ch0 = (tid >> 6) * 32;
        int idx = fidx[row];
        const float4* cr = (const float4*)(emb + (size_t)idx * NC + ch0);
        float* qb = out + OFF_Q + (size_t)b * (NC * NHW) + (size_t)ch0 * NHW + hw0 + row;
#pragma unroll
        for (int q = 0; q < 8; q++) {
            float4 v = __ldg(cr + q);
            qb[(size_t)(4 * q + 0) * NHW] = v.x;
            qb[(size_t)(4 * q + 1) * NHW] = v.y;
            qb[(size_t)(4 * q + 2) * NHW] = v.z;
            qb[(size_t)(4 * q + 3) * NHW] = v.w;
        }
    }
}

// ---------------------------------------------------------------------------
// Kernel 2: finalize loss + perplexity (tiny, deterministic fixed-order)
// ---------------------------------------------------------------------------
__global__ void vq_finalize(float* __restrict__ out) {
    __shared__ float sp[512];
    __shared__ float sl[512];
    int t = threadIdx.x;
    float p = g_counts[t] * (1.0f / (float)NROW);
    sp[t] = p * logf(p + 1e-10f);
    // fixed-order: thread t sums partials [4t, 4t+4)
    float s = 0.f;
#pragma unroll
    for (int i = 0; i < 4; i++) s += g_lpart[4 * t + i];
    sl[t] = s;
    __syncthreads();
#pragma unroll
    for (int o = 256; o >= 1; o >>= 1) {
        if (t < o) { sp[t] += sp[t + o]; sl[t] += sl[t + o]; }
        __syncthreads();
    }
    if (t == 0) {
        out[OFF_PERP] = expf(-sp[0]);
        out[OFF_LOSS] = 0.25f * sl[0] * (1.0f / 8388608.0f);  // BETA * mean over N*C
    }
}

// ---------------------------------------------------------------------------
// Launch
// ---------------------------------------------------------------------------
extern "C" void kernel_launch(void* const* d_in, const int* in_sizes, int n_in,
                              void* d_out, int out_size) {
    const float* x = (const float*)d_in[0];
    const float* e = (const float*)d_in[1];
    if (n_in >= 2 && in_sizes[0] == NK * NC) {
        const float* tmp = x; x = e; e = tmp;
    }
    float* out = (float*)d_out;

    const int SMEM1 = (64 * 64 + 64 * 132 + 128) * (int)sizeof(float);  // 50688 B
    cudaFuncSetAttribute(vq_argmin, cudaFuncAttributeMaxDynamicSharedMemorySize, SMEM1);

    vq_init<<<1, 512>>>(e);
    vq_argmin<<<NCTA, 128, SMEM1>>>(x, e, out);
    vq_finalize<<<1, 512>>>(out);
}